// round 13
// baseline (speedup 1.0000x reference)
#include <cuda_runtime.h>
#include <cuda_bf16.h>
#include <cuda_fp16.h>
#include <cstdint>
#include <math.h>

#define Bb   2
#define Tt   2048
#define HIDD 2048
#define NH   16
#define KVH  4
#define HD   128
#define Mrows (Bb*Tt)

// ---------------- scratch (device globals: allocation-free) ----------------
__device__ float g_Q[(size_t)Bb*NH*Tt*HD];    // [B, NH, T, HD]
__device__ float g_K[(size_t)Bb*KVH*Tt*HD];   // [B, KVH, T, HD]
__device__ float g_V[(size_t)Bb*KVH*Tt*HD];   // [B, KVH, T, HD]
__device__ float g_ctx[(size_t)Bb*Tt*HIDD];   // [B*T, HID]

// ================= mma.sync helpers (compute_103-safe) =====================
__device__ __forceinline__ uint32_t smem_u32(const void* p) {
    uint32_t a;
    asm("{ .reg .u64 t; cvta.to.shared.u64 t, %1; cvt.u32.u64 %0, t; }" : "=r"(a) : "l"(p));
    return a;
}
__device__ __forceinline__ void ldm_x4(uint32_t& r0, uint32_t& r1, uint32_t& r2,
                                       uint32_t& r3, uint32_t addr) {
    asm volatile("ldmatrix.sync.aligned.m8n8.x4.shared.b16 {%0,%1,%2,%3}, [%4];"
                 : "=r"(r0), "=r"(r1), "=r"(r2), "=r"(r3) : "r"(addr));
}
__device__ __forceinline__ void ldm_x4_trans(uint32_t& r0, uint32_t& r1, uint32_t& r2,
                                             uint32_t& r3, uint32_t addr) {
    asm volatile("ldmatrix.sync.aligned.m8n8.x4.trans.shared.b16 {%0,%1,%2,%3}, [%4];"
                 : "=r"(r0), "=r"(r1), "=r"(r2), "=r"(r3) : "r"(addr));
}
// fp16 mma
__device__ __forceinline__ void mma16816h(float* c, uint32_t a0, uint32_t a1,
                                          uint32_t a2, uint32_t a3,
                                          uint32_t b0, uint32_t b1) {
    asm volatile(
        "mma.sync.aligned.m16n8k16.row.col.f32.f16.f16.f32 "
        "{%0,%1,%2,%3}, {%4,%5,%6,%7}, {%8,%9}, {%0,%1,%2,%3};"
        : "+f"(c[0]), "+f"(c[1]), "+f"(c[2]), "+f"(c[3])
        : "r"(a0), "r"(a1), "r"(a2), "r"(a3), "r"(b0), "r"(b1));
}
__device__ __forceinline__ float ex2(float x) {
    float r;
    asm("ex2.approx.f32 %0, %1;" : "=f"(r) : "f"(x));
    return r;
}

// ---- fp16 split helpers ----
__device__ __forceinline__ void split4h(float4 v, uint32_t& h0, uint32_t& h1,
                                        uint32_t& l0, uint32_t& l1) {
    __half2 a = __floats2half2_rn(v.x, v.y);
    __half2 b = __floats2half2_rn(v.z, v.w);
    __half2 ra = __floats2half2_rn(v.x - __half2float(a.x),
                                   v.y - __half2float(a.y));
    __half2 rb = __floats2half2_rn(v.z - __half2float(b.x),
                                   v.w - __half2float(b.y));
    h0 = *(uint32_t*)&a; h1 = *(uint32_t*)&b;
    l0 = *(uint32_t*)&ra; l1 = *(uint32_t*)&rb;
}
__device__ __forceinline__ void round4h(float4 v, uint32_t& h0, uint32_t& h1) {
    __half2 a = __floats2half2_rn(v.x, v.y);
    __half2 b = __floats2half2_rn(v.z, v.w);
    h0 = *(uint32_t*)&a; h1 = *(uint32_t*)&b;
}
__device__ __forceinline__ uint32_t pack_h(float x, float y) {
    __half2 h = __floats2half2_rn(x, y);
    return *(uint32_t*)&h;
}

// ======== fp16 2-term GEMM body: C[M,N] = A[M,K] @ W[K,N] ==================
// 128x128 tile, BK=32, 1 CTA/SM, register-preload software pipeline:
// next chunk's A/B float4s loaded during current chunk's MMAs.
#define SP  40
#define BSP 136

__device__ __forceinline__ void gemm_body(
    const float* __restrict__ A, const float* __restrict__ W,
    float* __restrict__ C, int N, int K, int mode, int H, int m0, int n0)
{
    __shared__ __align__(16) uint16_t sAh[128 * SP];
    __shared__ __align__(16) uint16_t sAl[128 * SP];
    __shared__ __align__(16) uint16_t sBh[32 * BSP];

    const uint32_t uAh = smem_u32(sAh), uAl = smem_u32(sAl);
    const uint32_t uBh = smem_u32(sBh);

    int tid = threadIdx.x;
    int wid = tid >> 5, lane = tid & 31;
    int wm = wid >> 2, wn = wid & 3;

    int arow = tid >> 1;
    int acb  = (tid & 1) << 4;
    int bk0  = tid >> 5;
    int bn4  = (tid & 31) << 2;

    const float* apg = A + (size_t)(m0 + arow) * K + acb;
    const float* bpg = W + (size_t)bk0 * N + n0 + bn4;

    float acc[4][4][4];
    #pragma unroll
    for (int i = 0; i < 4; ++i)
        #pragma unroll
        for (int j = 0; j < 4; ++j)
            #pragma unroll
            for (int e = 0; e < 4; ++e) acc[i][j][e] = 0.f;

    int chunks = K >> 5;

    // ---- preload chunk 0 ----
    float4 ar[4], br[4];
    #pragma unroll
    for (int c = 0; c < 4; ++c) ar[c] = *(const float4*)(apg + (c << 2));
    #pragma unroll
    for (int it = 0; it < 4; ++it) br[it] = *(const float4*)(bpg + (size_t)(it << 3) * N);

    for (int i = 0; i < chunks; ++i) {
        // ---- convert + store staged chunk ----
        #pragma unroll
        for (int c = 0; c < 4; ++c) {
            uint32_t h0, h1, l0, l1;
            split4h(ar[c], h0, h1, l0, l1);
            uint32_t off = (uint32_t)(arow * SP + acb + (c << 2)) << 1;
            *(uint32_t*)((char*)sAh + off)     = h0;
            *(uint32_t*)((char*)sAh + off + 4) = h1;
            *(uint32_t*)((char*)sAl + off)     = l0;
            *(uint32_t*)((char*)sAl + off + 4) = l1;
        }
        #pragma unroll
        for (int it = 0; it < 4; ++it) {
            uint32_t h0, h1;
            round4h(br[it], h0, h1);
            uint32_t off = (uint32_t)((bk0 + (it << 3)) * BSP + bn4) << 1;
            *(uint32_t*)((char*)sBh + off)     = h0;
            *(uint32_t*)((char*)sBh + off + 4) = h1;
        }
        __syncthreads();

        // ---- issue next chunk's global loads (hidden by MMAs below) ----
        if (i + 1 < chunks) {
            int k0 = (i + 1) << 5;
            #pragma unroll
            for (int c = 0; c < 4; ++c) ar[c] = *(const float4*)(apg + k0 + (c << 2));
            #pragma unroll
            for (int it = 0; it < 4; ++it)
                br[it] = *(const float4*)(bpg + (size_t)(k0 + (it << 3)) * N);
        }

        int r16 = lane & 15, hsel = lane >> 4;
        #pragma unroll
        for (int ks = 0; ks < 2; ++ks) {
            uint32_t bh[2][4];
            #pragma unroll
            for (int j2 = 0; j2 < 2; ++j2) {
                uint32_t boff = (uint32_t)((ks * 16 + r16) * BSP +
                                           (wn << 5) + (j2 << 4) + (hsel << 3)) << 1;
                ldm_x4_trans(bh[j2][0], bh[j2][1], bh[j2][2], bh[j2][3], uBh + boff);
            }
            #pragma unroll
            for (int ii = 0; ii < 4; ++ii) {
                uint32_t aoff = (uint32_t)(((wm << 6) + (ii << 4) + r16) * SP +
                                           ks * 16 + (hsel << 3)) << 1;
                uint32_t ah0, ah1, ah2, ah3, al0, al1, al2, al3;
                ldm_x4(ah0, ah1, ah2, ah3, uAh + aoff);
                ldm_x4(al0, al1, al2, al3, uAl + aoff);
                #pragma unroll
                for (int j2 = 0; j2 < 2; ++j2) {
                    mma16816h(acc[ii][2*j2],   ah0, ah1, ah2, ah3, bh[j2][0], bh[j2][1]);
                    mma16816h(acc[ii][2*j2+1], ah0, ah1, ah2, ah3, bh[j2][2], bh[j2][3]);
                    mma16816h(acc[ii][2*j2],   al0, al1, al2, al3, bh[j2][0], bh[j2][1]);
                    mma16816h(acc[ii][2*j2+1], al0, al1, al2, al3, bh[j2][2], bh[j2][3]);
                }
            }
        }
        __syncthreads();
    }

    int g = lane >> 2, q = lane & 3;
    #pragma unroll
    for (int i = 0; i < 4; ++i) {
        #pragma unroll
        for (int half = 0; half < 2; ++half) {
            int m = m0 + (wm << 6) + (i << 4) + g + (half << 3);
            float* dst;
            if (mode == 0) {
                dst = C + (size_t)m * N + n0;
            } else {
                int b = m >> 11, t = m & (Tt - 1), h = n0 >> 7;
                dst = C + (((size_t)(b * H + h) * Tt + t) << 7);
            }
            #pragma unroll
            for (int j = 0; j < 4; ++j) {
                int nl = (wn << 5) + (j << 3) + (q << 1);
                float2 v;
                v.x = acc[i][j][half * 2];
                v.y = acc[i][j][half * 2 + 1];
                *(float2*)(dst + nl) = v;
            }
        }
    }
}

// ---- fused QKV projection: one launch, W selected by blockIdx.x ----
__global__ __launch_bounds__(256, 1) void qkv_gemm_kernel(
    const float* __restrict__ A,
    const float* __restrict__ Wq, const float* __restrict__ Wk,
    const float* __restrict__ Wv,
    float* __restrict__ Qo, float* __restrict__ Ko, float* __restrict__ Vo)
{
    int x = blockIdx.x;
    int m0 = blockIdx.y << 7;
    const float* W; float* C; int N, H, n0;
    if (x < 16)      { W = Wq; C = Qo; N = NH*HD;  H = NH;  n0 = x << 7; }
    else if (x < 20) { W = Wk; C = Ko; N = KVH*HD; H = KVH; n0 = (x - 16) << 7; }
    else             { W = Wv; C = Vo; N = KVH*HD; H = KVH; n0 = (x - 20) << 7; }
    gemm_body(A, W, C, N, HIDD, 1, H, m0, n0);
}

// ---- generic GEMM (output projection) ----
__global__ __launch_bounds__(256, 1) void tc_gemm_kernel(
    const float* __restrict__ A, const float* __restrict__ W,
    float* __restrict__ C, int N, int K, int mode, int H)
{
    gemm_body(A, W, C, N, K, mode, H, blockIdx.y << 7, blockIdx.x << 7);
}

// ---------------- RoPE (in-place on [B,H,T,HD]) ----------------
__global__ void rope_kernel(float* __restrict__ X, const float* __restrict__ cs,
                            const float* __restrict__ sn, int total)
{
    int i = blockIdx.x * blockDim.x + threadIdx.x;
    if (i >= total) return;
    int d = i & 63;
    int rest = i >> 6;
    int t = rest & (Tt - 1);
    float* row = X + ((size_t)rest << 7);
    float x1 = row[d], x2 = row[d + 64];
    float c1 = cs[(t << 7) + d],      s1 = sn[(t << 7) + d];
    float c2 = cs[(t << 7) + d + 64], s2 = sn[(t << 7) + d + 64];
    row[d]      = x1 * c1 - x2 * s1;
    row[d + 64] = x2 * c2 + x1 * s2;
}

// ========== Flash attention (fp16: 2-term S, 1-term PV; causal, GQA) =======
#define FSP 136

__global__ __launch_bounds__(256, 1) void flash_mma_kernel(
    const float* __restrict__ Q, const float* __restrict__ K,
    const float* __restrict__ V, float* __restrict__ ctx)
{
    extern __shared__ char fsm[];
    uint16_t* Qh = (uint16_t*)fsm;
    uint16_t* Ql = Qh + 128 * FSP;
    uint16_t* Kh = Ql + 128 * FSP;
    uint16_t* Vh = Kh + 64 * FSP;
    const uint32_t uQh = smem_u32(Qh), uQl = smem_u32(Ql);
    const uint32_t uKh = smem_u32(Kh), uVh = smem_u32(Vh);

    int tid = threadIdx.x, wid = tid >> 5, lane = tid & 31;
    int g = lane >> 2, qd = lane & 3;
    int r16 = lane & 15, hsel = lane >> 4;
    int qt = gridDim.x - 1 - blockIdx.x;
    int bh = blockIdx.y;
    int b = bh >> 4, h = bh & 15, kvh = h >> 2;

    const float* Qp = Q + (((size_t)(b * NH + h) * Tt + qt * 128) << 7);
    const float* Kp = K + (((size_t)(b * KVH + kvh) * Tt) << 7);
    const float* Vp = V + (((size_t)(b * KVH + kvh) * Tt) << 7);

    {
        int row = tid >> 1, cb = (tid & 1) << 6;
        const float* qp = Qp + ((size_t)row << 7) + cb;
        #pragma unroll
        for (int i = 0; i < 16; ++i) {
            float4 v = *(const float4*)(qp + (i << 2));
            uint32_t h0, h1, l0, l1;
            split4h(v, h0, h1, l0, l1);
            uint32_t off = (uint32_t)(row * FSP + cb + (i << 2)) << 1;
            *(uint32_t*)((char*)Qh + off)     = h0;
            *(uint32_t*)((char*)Qh + off + 4) = h1;
            *(uint32_t*)((char*)Ql + off)     = l0;
            *(uint32_t*)((char*)Ql + off + 4) = l1;
        }
    }

    float o[16][4];
    #pragma unroll
    for (int i = 0; i < 16; ++i)
        #pragma unroll
        for (int e = 0; e < 4; ++e) o[i][e] = 0.f;
    float m0 = -1e30f, m1 = -1e30f, l0 = 0.f, l1 = 0.f;
    const float alpha = 0.08838834764831845f * 1.4426950408889634f;

    int qbase = qt * 128 + wid * 16;
    int ntiles = 2 * qt + 2;

    int srow = tid >> 2, scb = (tid & 3) << 5;

    float4 kr[8], vr[8];
    {
        const float* kp = Kp + ((size_t)srow << 7) + scb;
        const float* vp = Vp + ((size_t)srow << 7) + scb;
        #pragma unroll
        for (int i = 0; i < 8; ++i) {
            kr[i] = *(const float4*)(kp + (i << 2));
            vr[i] = *(const float4*)(vp + (i << 2));
        }
    }

    for (int jt = 0; jt < ntiles; ++jt) {
        __syncthreads();
        #pragma unroll
        for (int i = 0; i < 8; ++i) {
            uint32_t off = (uint32_t)(srow * FSP + scb + (i << 2)) << 1;
            uint32_t h0, h1;
            round4h(kr[i], h0, h1);
            *(uint32_t*)((char*)Kh + off)     = h0;
            *(uint32_t*)((char*)Kh + off + 4) = h1;
            round4h(vr[i], h0, h1);
            *(uint32_t*)((char*)Vh + off)     = h0;
            *(uint32_t*)((char*)Vh + off + 4) = h1;
        }
        __syncthreads();

        if (jt + 1 < ntiles) {
            const float* kp = Kp + ((size_t)((jt + 1) * 64 + srow) << 7) + scb;
            const float* vp = Vp + ((size_t)((jt + 1) * 64 + srow) << 7) + scb;
            #pragma unroll
            for (int i = 0; i < 8; ++i) {
                kr[i] = *(const float4*)(kp + (i << 2));
                vr[i] = *(const float4*)(vp + (i << 2));
            }
        }

        float s[8][4];
        #pragma unroll
        for (int t8 = 0; t8 < 8; ++t8)
            #pragma unroll
            for (int e = 0; e < 4; ++e) s[t8][e] = 0.f;

        #pragma unroll
        for (int ks = 0; ks < 8; ++ks) {
            uint32_t aoff = (uint32_t)((wid * 16 + r16) * FSP + ks * 16 + (hsel << 3)) << 1;
            uint32_t ah0, ah1, ah2, ah3, al0, al1, al2, al3;
            ldm_x4(ah0, ah1, ah2, ah3, uQh + aoff);
            ldm_x4(al0, al1, al2, al3, uQl + aoff);
            #pragma unroll
            for (int nt = 0; nt < 4; ++nt) {
                uint32_t koff = (uint32_t)((nt * 16 + r16) * FSP + ks * 16 + (hsel << 3)) << 1;
                uint32_t kh0, kh1, kh2, kh3;
                ldm_x4(kh0, kh1, kh2, kh3, uKh + koff);
                mma16816h(s[2*nt],   ah0, ah1, ah2, ah3, kh0, kh2);
                mma16816h(s[2*nt+1], ah0, ah1, ah2, ah3, kh1, kh3);
                mma16816h(s[2*nt],   al0, al1, al2, al3, kh0, kh2);
                mma16816h(s[2*nt+1], al0, al1, al2, al3, kh1, kh3);
            }
        }

        int kvb = jt * 64;
        int qr0 = qbase + g;
        bool needmask = (kvb + 63 > qbase);
        #pragma unroll
        for (int t8 = 0; t8 < 8; ++t8) {
            #pragma unroll
            for (int e = 0; e < 4; ++e) {
                float val = s[t8][e] * alpha;
                if (needmask) {
                    int col = kvb + t8 * 8 + qd * 2 + (e & 1);
                    int row = (e < 2) ? qr0 : qr0 + 8;
                    if (col > row) val = -1e30f;
                }
                s[t8][e] = val;
            }
        }

        float tm0 = -1e30f, tm1 = -1e30f;
        #pragma unroll
        for (int t8 = 0; t8 < 8; ++t8) {
            tm0 = fmaxf(tm0, fmaxf(s[t8][0], s[t8][1]));
            tm1 = fmaxf(tm1, fmaxf(s[t8][2], s[t8][3]));
        }
        tm0 = fmaxf(tm0, __shfl_xor_sync(0xffffffffu, tm0, 1));
        tm0 = fmaxf(tm0, __shfl_xor_sync(0xffffffffu, tm0, 2));
        tm1 = fmaxf(tm1, __shfl_xor_sync(0xffffffffu, tm1, 1));
        tm1 = fmaxf(tm1, __shfl_xor_sync(0xffffffffu, tm1, 2));
        float nm0 = fmaxf(m0, tm0), nm1 = fmaxf(m1, tm1);
        float c0 = ex2(m0 - nm0), c1 = ex2(m1 - nm1);
        m0 = nm0; m1 = nm1;

        float ps0 = 0.f, ps1 = 0.f;
        #pragma unroll
        for (int t8 = 0; t8 < 8; ++t8) {
            s[t8][0] = ex2(s[t8][0] - nm0);
            s[t8][1] = ex2(s[t8][1] - nm0);
            s[t8][2] = ex2(s[t8][2] - nm1);
            s[t8][3] = ex2(s[t8][3] - nm1);
            ps0 += s[t8][0] + s[t8][1];
            ps1 += s[t8][2] + s[t8][3];
        }
        ps0 += __shfl_xor_sync(0xffffffffu, ps0, 1);
        ps0 += __shfl_xor_sync(0xffffffffu, ps0, 2);
        ps1 += __shfl_xor_sync(0xffffffffu, ps1, 1);
        ps1 += __shfl_xor_sync(0xffffffffu, ps1, 2);
        l0 = l0 * c0 + ps0;
        l1 = l1 * c1 + ps1;

        #pragma unroll
        for (int dt = 0; dt < 16; ++dt) {
            o[dt][0] *= c0; o[dt][1] *= c0;
            o[dt][2] *= c1; o[dt][3] *= c1;
        }

        #pragma unroll
        for (int j = 0; j < 4; ++j) {
            uint32_t ph0 = pack_h(s[2*j][0],   s[2*j][1]);
            uint32_t ph1 = pack_h(s[2*j][2],   s[2*j][3]);
            uint32_t ph2 = pack_h(s[2*j+1][0], s[2*j+1][1]);
            uint32_t ph3 = pack_h(s[2*j+1][2], s[2*j+1][3]);
            #pragma unroll
            for (int dt = 0; dt < 8; ++dt) {
                uint32_t voff = (uint32_t)((j * 16 + r16) * FSP + dt * 16 + (hsel << 3)) << 1;
                uint32_t vh0, vh1, vh2, vh3;
                ldm_x4_trans(vh0, vh1, vh2, vh3, uVh + voff);
                mma16816h(o[2*dt],   ph0, ph1, ph2, ph3, vh0, vh1);
                mma16816h(o[2*dt+1], ph0, ph1, ph2, ph3, vh2, vh3);
            }
        }
    }

    float li0 = 1.f / l0, li1 = 1.f / l1;
    int t0 = qbase + g;
    float* dst0 = ctx + (size_t)(b * Tt + t0) * HIDD + h * HD;
    float* dst1 = ctx + (size_t)(b * Tt + t0 + 8) * HIDD + h * HD;
    #pragma unroll
    for (int dt = 0; dt < 16; ++dt) {
        int col = dt * 8 + qd * 2;
        float2 w0 = make_float2(o[dt][0] * li0, o[dt][1] * li0);
        float2 w1 = make_float2(o[dt][2] * li1, o[dt][3] * li1);
        *(float2*)(dst0 + col) = w0;
        *(float2*)(dst1 + col) = w1;
    }
}

// ---------------- launch ----------------
extern "C" void kernel_launch(void* const* d_in, const int* in_sizes, int n_in,
                              void* d_out, int out_size)
{
    const float* hs   = (const float*)d_in[0];
    const float* cosp = (const float*)d_in[2];
    const float* sinp = (const float*)d_in[3];
    const float* Wq   = (const float*)d_in[4];
    const float* Wk   = (const float*)d_in[5];
    const float* Wv   = (const float*)d_in[6];
    const float* Wo   = (const float*)d_in[7];
    float* out = (float*)d_out;

    float *pQ, *pK, *pV, *pC;
    cudaGetSymbolAddress((void**)&pQ, g_Q);
    cudaGetSymbolAddress((void**)&pK, g_K);
    cudaGetSymbolAddress((void**)&pV, g_V);
    cudaGetSymbolAddress((void**)&pC, g_ctx);

    // Fused QKV projection (fp16 2-term, register-preload pipeline)
    qkv_gemm_kernel<<<dim3(24, 32), 256>>>(hs, Wq, Wk, Wv, pQ, pK, pV);

    // RoPE on Q and K
    int totQ = Bb * NH  * Tt * 64;
    int totK = Bb * KVH * Tt * 64;
    rope_kernel<<<totQ / 256, 256>>>(pQ, cosp, sinp, totQ);
    rope_kernel<<<totK / 256, 256>>>(pK, cosp, sinp, totK);

    // Flash attention (fp16 2-term S, 1-term PV)
    size_t fsh = (size_t)(2 * 128 * FSP + 2 * 64 * FSP) * sizeof(uint16_t); // 104448
    cudaFuncSetAttribute(flash_mma_kernel, cudaFuncAttributeMaxDynamicSharedMemorySize, (int)fsh);
    flash_mma_kernel<<<dim3(Tt/128, Bb*NH), 256, fsh>>>(pQ, pK, pV, pC);

    // Output projection (fp16 2-term) -> d_out
    tc_gemm_kernel<<<dim3(16, 32), 256>>>(pC, Wo, out, HIDD, HIDD, 0, 0);
}